// round 9
// baseline (speedup 1.0000x reference)
#include <cuda_runtime.h>
#include <cstdint>

#define FULLMASK 0xffffffffu

constexpr int B_   = 64;
constexpr int N_   = 1024;
constexpr int D_   = 64;
constexpr int NNODES = B_ * N_;                 // 65536
constexpr int EDGES  = 1 << 20;                 // 1,048,576
constexpr int ROW_WORDS = N_ / 32;              // 32
constexpr int ADJ_WORDS = NNODES * ROW_WORDS;   // 2,097,152 (8 MB)

constexpr int ROWS_PER_BLOCK = 128;
constexpr int THREADS = 256;                     // 8 warps, 16 rows/warp
constexpr int BLOCKS_PER_GRAPH = N_ / ROWS_PER_BLOCK;  // 8
constexpr int LISTCAP  = 320;
constexpr int W_STRIDE = 68;

// k_aggregate dynamic smem layout (floats):
//   S[128][64] (chunk-swizzled), W[64][68], lists 8*320 ushort
constexpr int SM_S_OFF    = 0;
constexpr int SM_W_OFF    = ROWS_PER_BLOCK * 64;              // 8192
constexpr int SM_LIST_OFF = SM_W_OFF + 64 * W_STRIDE;         // 12544
constexpr int SM_BYTES    = SM_LIST_OFF * 4 + 8 * LISTCAP * 2; // 55296

// Scratch (zero-initialized at load; every call restores the zeros)
__device__ unsigned g_adj[ADJ_WORDS];
__device__ unsigned g_pooled[B_ * D_];
__device__ int g_cnt[B_];

// Order-preserving float <-> uint map for atomicMax on floats
__device__ __forceinline__ unsigned fmap(float f) {
    unsigned u = __float_as_uint(f);
    return (u & 0x80000000u) ? ~u : (u | 0x80000000u);
}
__device__ __forceinline__ float funmap(unsigned u) {
    return (u & 0x80000000u) ? __uint_as_float(u ^ 0x80000000u)
                             : __uint_as_float(~u);
}

// ---- packed f32x2 helpers (Blackwell) ----
__device__ __forceinline__ unsigned long long pack2(float lo, float hi) {
    unsigned long long r;
    unsigned a = __float_as_uint(lo), b = __float_as_uint(hi);
    asm("mov.b64 %0, {%1, %2};" : "=l"(r) : "r"(a), "r"(b));
    return r;
}
__device__ __forceinline__ unsigned long long fma2(unsigned long long a,
                                                   unsigned long long b,
                                                   unsigned long long c) {
    unsigned long long d;
    asm("fma.rn.f32x2 %0, %1, %2, %3;" : "=l"(d) : "l"(a), "l"(b), "l"(c));
    return d;
}
__device__ __forceinline__ unsigned long long add2(unsigned long long a,
                                                   unsigned long long b) {
    unsigned long long d;
    asm("add.rn.f32x2 %0, %1, %2;" : "=l"(d) : "l"(a), "l"(b));
    return d;
}
__device__ __forceinline__ float lo2(unsigned long long u) { return __uint_as_float((unsigned)u); }
__device__ __forceinline__ float hi2(unsigned long long u) { return __uint_as_float((unsigned)(u >> 32)); }

union F4U {
    float4 f;
    unsigned long long u[2];
};

// W bank swizzle: 4-float chunks; upper-half chunks rotated by 4 words
__device__ __host__ __forceinline__ int wphys(int dc) {
    return (dc < 32) ? dc : ((((dc + 4) & 31)) | 32);
}

// ---------------------------------------------------------------------------
// 1) Edge scatter into bitmap (idempotent -> exact dedup). 2 edges/thread.
//    int64/int32 detection done per-block from L2 (no separate launch).
// ---------------------------------------------------------------------------
__global__ void k_scatter(const void* ei_raw) {
    __shared__ int s_is64;
    if (threadIdx.x == 0) {
        const long long* p = (const long long*)ei_raw;
        int is64 = 1;
        for (int i = 0; i < 16; i++) {
            long long v = p[i];
            if (v < 0 || v > 65535) is64 = 0;
        }
        s_is64 = is64;
    }
    __syncthreads();

    int e2 = blockIdx.x * blockDim.x + threadIdx.x;   // pair index
    if (e2 >= EDGES / 2) return;
    int s0, t0, s1, t1;
    if (s_is64) {
        const longlong2* ps = (const longlong2*)ei_raw;
        longlong2 sv = ps[e2];
        longlong2 tv = ps[EDGES / 2 + e2];
        s0 = (int)sv.x; s1 = (int)sv.y;
        t0 = (int)tv.x; t1 = (int)tv.y;
    } else {
        const int2* ps = (const int2*)ei_raw;
        int2 sv = ps[e2];
        int2 tv = ps[EDGES / 2 + e2];
        s0 = sv.x; s1 = sv.y;
        t0 = tv.x; t1 = tv.y;
    }
    int l0 = t0 & (N_ - 1);
    int l1 = t1 & (N_ - 1);
    atomicOr(&g_adj[s0 * ROW_WORDS + (l0 >> 5)], 1u << (l0 & 31));
    atomicOr(&g_adj[s1 * ROW_WORDS + (l1 >> 5)], 1u << (l1 & 31));
}

// ---------------------------------------------------------------------------
// 2) Fused gather + transform + max-pool + (last block per graph) MLP head.
// ---------------------------------------------------------------------------
__global__ __launch_bounds__(THREADS)
void k_aggregate(const float* __restrict__ x,
                 const float* __restrict__ W,
                 const float* __restrict__ bias,
                 const float* __restrict__ w1, const float* __restrict__ b1,
                 const float* __restrict__ w2, const float* __restrict__ b2,
                 const float* __restrict__ w3, const float* __restrict__ b3,
                 float* __restrict__ out) {
    extern __shared__ float smem[];
    float* S   = smem + SM_S_OFF;
    float* Wsh = smem + SM_W_OFF;
    unsigned short* listAll = (unsigned short*)(smem + SM_LIST_OFF);

    const int tid  = threadIdx.x;
    const int warp = tid >> 5;
    const int lane = tid & 31;
    const int g    = blockIdx.x >> 3;            // 8 blocks/graph

    // ---- stage W (swizzled) ----
    for (int idx = tid; idx < 64 * 64; idx += THREADS) {
        int k = idx >> 6, d = idx & 63;
        Wsh[k * W_STRIDE + wphys(d & ~3) + (d & 3)] = W[idx];
    }

    // ---- Phase A: gather ----
    {
        const int h   = lane >> 4;
        const int l16 = lane & 15;
        const int off = l16 << 2;
        unsigned short* lst = listAll + warp * LISTCAP;
        const float* xg = x + ((size_t)g << 16);

        const int rowBase = blockIdx.x * ROWS_PER_BLOCK + warp * 16;
        unsigned wordNext = g_adj[rowBase * ROW_WORDS + lane];

        for (int i = 0; i < 16; i++) {
            const int lr = warp * 16 + i;
            unsigned word = wordNext;
            if (i < 15)
                wordNext = g_adj[(rowBase + i + 1) * ROW_WORDS + lane];
            g_adj[(rowBase + i) * ROW_WORDS + lane] = 0u;  // restore zeros

            // decode bitmap row -> compact neighbor list
            int cnt = __popc(word);
            int pre = cnt;
#pragma unroll
            for (int o = 1; o < 32; o <<= 1) {
                int v = __shfl_up_sync(FULLMASK, pre, o);
                if (lane >= o) pre += v;
            }
            int deg = __shfl_sync(FULLMASK, pre, 31);
            pre -= cnt;
            while (word) {
                int b = __ffs(word) - 1;
                word &= word - 1;
                if (pre < LISTCAP) lst[pre] = (unsigned short)((lane << 5) | b);
                pre++;
            }
            if (deg > LISTCAP) deg = LISTCAP;
            __syncwarp();

            // half-warp pair gather, unrolled x4, two f32x2 accumulator chains
            unsigned long long a0 = 0ull, a1 = 0ull, b0 = 0ull, b1 = 0ull;
            const int nfull = deg >> 1;
            int t = 0;
            for (; t + 4 <= nfull; t += 4) {
                int i0 = (int)lst[2 * t + h];
                int i1 = (int)lst[2 * (t + 1) + h];
                int i2 = (int)lst[2 * (t + 2) + h];
                int i3 = (int)lst[2 * (t + 3) + h];
                F4U v0, v1, v2, v3;
                v0.f = __ldg((const float4*)(xg + (i0 << 6) + off));
                v1.f = __ldg((const float4*)(xg + (i1 << 6) + off));
                v2.f = __ldg((const float4*)(xg + (i2 << 6) + off));
                v3.f = __ldg((const float4*)(xg + (i3 << 6) + off));
                a0 = add2(a0, v0.u[0]); a1 = add2(a1, v0.u[1]);
                b0 = add2(b0, v1.u[0]); b1 = add2(b1, v1.u[1]);
                a0 = add2(a0, v2.u[0]); a1 = add2(a1, v2.u[1]);
                b0 = add2(b0, v3.u[0]); b1 = add2(b1, v3.u[1]);
            }
            for (; t < nfull; t++) {
                int ni = (int)lst[2 * t + h];
                F4U v;
                v.f = __ldg((const float4*)(xg + (ni << 6) + off));
                a0 = add2(a0, v.u[0]);
                a1 = add2(a1, v.u[1]);
            }
            if ((deg & 1) && h == 0) {
                int ni = (int)lst[deg - 1];
                F4U v;
                v.f = __ldg((const float4*)(xg + (ni << 6) + off));
                b0 = add2(b0, v.u[0]);
                b1 = add2(b1, v.u[1]);
            }
            a0 = add2(a0, b0);
            a1 = add2(a1, b1);

            float s0 = lo2(a0), s1 = hi2(a0), s2 = lo2(a1), s3 = hi2(a1);
            s0 += __shfl_xor_sync(FULLMASK, s0, 16);
            s1 += __shfl_xor_sync(FULLMASK, s1, 16);
            s2 += __shfl_xor_sync(FULLMASK, s2, 16);
            s3 += __shfl_xor_sync(FULLMASK, s3, 16);
            if (h == 0) {
                // chunk-rotation swizzle: logical chunk l16 -> phys (l16 + row/4) & 15
                int pc = ((l16 + (lr >> 2)) & 15) << 2;
                *(float4*)&S[(lr << 6) + pc] = make_float4(s0, s1, s2, s3);
            }
            __syncwarp();
        }
    }
    __syncthreads();

    // ---- Phase B: Y = S@W + bias, 4 rows x 8 dims / thread, f32x2,
    //      chunked-k float4 S reads (conflict-free via rotation swizzle) ----
    const int d0    = (lane & 7) * 8;
    const int rsub  = lane >> 3;
    const int rbase = warp * 16 + rsub * 4;
    const int rq    = rbase >> 2;                // row>>2, constant for i<4
    const int pc0   = wphys(d0);
    const int pc1   = wphys(d0 + 4);

    unsigned long long acc[4][4];
    {
        unsigned long long bp[4];
#pragma unroll
        for (int p = 0; p < 4; p++)
            bp[p] = pack2(__ldg(&bias[d0 + 2 * p]), __ldg(&bias[d0 + 2 * p + 1]));
#pragma unroll
        for (int i = 0; i < 4; i++)
#pragma unroll
            for (int p = 0; p < 4; p++) acc[i][p] = bp[p];
    }

#pragma unroll 4
    for (int kc = 0; kc < 16; kc++) {
        F4U sv[4];
        const int pcs = ((kc + rq) & 15) << 2;
#pragma unroll
        for (int i = 0; i < 4; i++)
            sv[i].f = *(const float4*)&S[((rbase + i) << 6) + pcs];
#pragma unroll
        for (int kk = 0; kk < 4; kk++) {
            const int k = kc * 4 + kk;
            F4U wa, wb;
            wa.f = *(const float4*)&Wsh[k * W_STRIDE + pc0];
            wb.f = *(const float4*)&Wsh[k * W_STRIDE + pc1];
#pragma unroll
            for (int i = 0; i < 4; i++) {
                float s = (kk == 0) ? sv[i].f.x : (kk == 1) ? sv[i].f.y
                        : (kk == 2) ? sv[i].f.z : sv[i].f.w;
                unsigned long long sp = pack2(s, s);
                acc[i][0] = fma2(sp, wa.u[0], acc[i][0]);
                acc[i][1] = fma2(sp, wa.u[1], acc[i][1]);
                acc[i][2] = fma2(sp, wb.u[0], acc[i][2]);
                acc[i][3] = fma2(sp, wb.u[1], acc[i][3]);
            }
        }
    }

    // ---- max-pool epilogue ----
    float m[8];
#pragma unroll
    for (int p = 0; p < 4; p++) {
        float m0 = lo2(acc[0][p]), m1 = hi2(acc[0][p]);
#pragma unroll
        for (int i = 1; i < 4; i++) {
            m0 = fmaxf(m0, lo2(acc[i][p]));
            m1 = fmaxf(m1, hi2(acc[i][p]));
        }
        m[2 * p] = m0;
        m[2 * p + 1] = m1;
    }
#pragma unroll
    for (int j = 0; j < 8; j++) {
        m[j] = fmaxf(m[j], __shfl_xor_sync(FULLMASK, m[j], 8));
        m[j] = fmaxf(m[j], __shfl_xor_sync(FULLMASK, m[j], 16));
    }
    if (rsub == 0) {
#pragma unroll
        for (int j = 0; j < 8; j++)
            atomicMax(&g_pooled[g * 64 + d0 + j], fmap(m[j]));
    }

    // ---- last block of this graph runs the MLP head inline ----
    __shared__ int s_last;
    __shared__ float mh[64];
    __shared__ float mred[4][64];
    __shared__ float moutred[2];

    __threadfence();            // order this block's atomicMax before counter
    __syncthreads();
    if (tid == 0)
        s_last = (atomicAdd(&g_cnt[g], 1) == BLOCKS_PER_GRAPH - 1);
    __syncthreads();
    if (!s_last) return;
    __threadfence();            // acquire: other blocks' pooled maxes visible

    const int d = tid & 63;
    const int q = tid >> 6;     // 0..3, k-chunk
    if (tid < 64) {
        mh[tid] = funmap(g_pooled[g * 64 + tid]);
        g_pooled[g * 64 + tid] = 0u;     // restore zeros for next call
    }
    if (tid == 0) g_cnt[g] = 0;
    __syncthreads();

    // layer 1
    {
        float p = 0.f;
        const int k0 = q * 16;
#pragma unroll
        for (int k = 0; k < 16; k++)
            p = fmaf(mh[k0 + k], __ldg(&w1[(k0 + k) * 64 + d]), p);
        mred[q][d] = p;
        __syncthreads();
        if (tid < 64)
            mh[d] = tanhf(mred[0][d] + mred[1][d] + mred[2][d] + mred[3][d]
                          + __ldg(&b1[d]));
        __syncthreads();
    }
    // layer 2
    {
        float p = 0.f;
        const int k0 = q * 16;
#pragma unroll
        for (int k = 0; k < 16; k++)
            p = fmaf(mh[k0 + k], __ldg(&w2[(k0 + k) * 64 + d]), p);
        mred[q][d] = p;
        __syncthreads();
        if (tid < 64)
            mh[d] = tanhf(mred[0][d] + mred[1][d] + mred[2][d] + mred[3][d]
                          + __ldg(&b2[d]));
        __syncthreads();
    }
    // layer 3
    if (tid < 64) {
        float p = mh[tid] * __ldg(&w3[tid]);
#pragma unroll
        for (int o = 16; o; o >>= 1) p += __shfl_xor_sync(FULLMASK, p, o);
        if ((tid & 31) == 0) moutred[tid >> 5] = p;
    }
    __syncthreads();
    if (tid == 0) out[g] = moutred[0] + moutred[1] + __ldg(&b3[0]);
}

// ---------------------------------------------------------------------------
extern "C" void kernel_launch(void* const* d_in, const int* in_sizes, int n_in,
                              void* d_out, int out_size) {
    const float* x      = (const float*)d_in[0];
    const void*  eidx   = d_in[1];
    const float* weight = (const float*)d_in[4];
    const float* bias   = (const float*)d_in[5];
    const float* w1     = (const float*)d_in[6];
    const float* b1     = (const float*)d_in[7];
    const float* w2     = (const float*)d_in[8];
    const float* b2     = (const float*)d_in[9];
    const float* w3     = (const float*)d_in[10];
    const float* b3     = (const float*)d_in[11];
    float* out = (float*)d_out;

    cudaFuncSetAttribute(k_aggregate, cudaFuncAttributeMaxDynamicSharedMemorySize, SM_BYTES);

    k_scatter<<<(EDGES / 2 + 255) / 256, 256>>>(eidx);

    k_aggregate<<<NNODES / ROWS_PER_BLOCK, THREADS, SM_BYTES>>>(
        x, weight, bias, w1, b1, w2, b2, w3, b3, out);
}

// round 10
// speedup vs baseline: 1.2962x; 1.2962x over previous
#include <cuda_runtime.h>
#include <cstdint>

#define FULLMASK 0xffffffffu

constexpr int B_   = 64;
constexpr int N_   = 1024;
constexpr int D_   = 64;
constexpr int NNODES = B_ * N_;                 // 65536
constexpr int EDGES  = 1 << 20;                 // 1,048,576
constexpr int ROW_WORDS = N_ / 32;              // 32
constexpr int ADJ_WORDS = NNODES * ROW_WORDS;   // 2,097,152 (8 MB)

constexpr int ROWS_PER_BLOCK = 128;
constexpr int THREADS = 256;                     // 8 warps, 16 rows/warp
constexpr int BLOCKS_PER_GRAPH = N_ / ROWS_PER_BLOCK;  // 8
constexpr int LISTCAP  = 192;
constexpr int W_STRIDE = 68;

// k_aggregate dynamic smem layout (floats):
//   S[128][64] (chunk-swizzled), W[64][68], lists 8*192 ushort
constexpr int SM_S_OFF    = 0;
constexpr int SM_W_OFF    = ROWS_PER_BLOCK * 64;              // 8192
constexpr int SM_LIST_OFF = SM_W_OFF + 64 * W_STRIDE;         // 12544
constexpr int SM_BYTES    = SM_LIST_OFF * 4 + 8 * LISTCAP * 2; // 50176+3072=53248

// Scratch (zero-initialized at load; every call restores the zeros)
__device__ unsigned g_adj[ADJ_WORDS];
__device__ unsigned g_pooled[B_ * D_];
__device__ int g_cnt[B_];

// Order-preserving float <-> uint map for atomicMax on floats
__device__ __forceinline__ unsigned fmap(float f) {
    unsigned u = __float_as_uint(f);
    return (u & 0x80000000u) ? ~u : (u | 0x80000000u);
}
__device__ __forceinline__ float funmap(unsigned u) {
    return (u & 0x80000000u) ? __uint_as_float(u ^ 0x80000000u)
                             : __uint_as_float(~u);
}

// ---- packed f32x2 helpers (Blackwell) ----
__device__ __forceinline__ unsigned long long pack2(float lo, float hi) {
    unsigned long long r;
    unsigned a = __float_as_uint(lo), b = __float_as_uint(hi);
    asm("mov.b64 %0, {%1, %2};" : "=l"(r) : "r"(a), "r"(b));
    return r;
}
__device__ __forceinline__ unsigned long long fma2(unsigned long long a,
                                                   unsigned long long b,
                                                   unsigned long long c) {
    unsigned long long d;
    asm("fma.rn.f32x2 %0, %1, %2, %3;" : "=l"(d) : "l"(a), "l"(b), "l"(c));
    return d;
}
__device__ __forceinline__ unsigned long long add2(unsigned long long a,
                                                   unsigned long long b) {
    unsigned long long d;
    asm("add.rn.f32x2 %0, %1, %2;" : "=l"(d) : "l"(a), "l"(b));
    return d;
}
__device__ __forceinline__ float lo2(unsigned long long u) { return __uint_as_float((unsigned)u); }
__device__ __forceinline__ float hi2(unsigned long long u) { return __uint_as_float((unsigned)(u >> 32)); }

union F4U {
    float4 f;
    unsigned long long u[2];
};

// W bank swizzle: 4-float chunks; upper-half chunks rotated by 4 words
__device__ __host__ __forceinline__ int wphys(int dc) {
    return (dc < 32) ? dc : ((((dc + 4) & 31)) | 32);
}

// ---------------------------------------------------------------------------
// 1) Edge scatter into bitmap (idempotent -> exact dedup). 2 edges/thread.
//    int64/int32 detection done per-block from L2 (no separate launch).
// ---------------------------------------------------------------------------
__global__ void k_scatter(const void* ei_raw) {
    __shared__ int s_is64;
    if (threadIdx.x == 0) {
        const long long* p = (const long long*)ei_raw;
        int is64 = 1;
        for (int i = 0; i < 16; i++) {
            long long v = p[i];
            if (v < 0 || v > 65535) is64 = 0;
        }
        s_is64 = is64;
    }
    __syncthreads();

    int e2 = blockIdx.x * blockDim.x + threadIdx.x;   // pair index
    if (e2 >= EDGES / 2) return;
    int s0, t0, s1, t1;
    if (s_is64) {
        const longlong2* ps = (const longlong2*)ei_raw;
        longlong2 sv = ps[e2];
        longlong2 tv = ps[EDGES / 2 + e2];
        s0 = (int)sv.x; s1 = (int)sv.y;
        t0 = (int)tv.x; t1 = (int)tv.y;
    } else {
        const int2* ps = (const int2*)ei_raw;
        int2 sv = ps[e2];
        int2 tv = ps[EDGES / 2 + e2];
        s0 = sv.x; s1 = sv.y;
        t0 = tv.x; t1 = tv.y;
    }
    int l0 = t0 & (N_ - 1);
    int l1 = t1 & (N_ - 1);
    atomicOr(&g_adj[s0 * ROW_WORDS + (l0 >> 5)], 1u << (l0 & 31));
    atomicOr(&g_adj[s1 * ROW_WORDS + (l1 >> 5)], 1u << (l1 & 31));
}

// ---------------------------------------------------------------------------
// 2) Fused gather + transform + max-pool + (last block per graph) MLP head.
//    __launch_bounds__(256, 4): cap regs at 64 so occupancy stays smem-limited
//    (4 blocks/SM), not reg-limited. MLP-tail spills are once-per-8-blocks.
// ---------------------------------------------------------------------------
__global__ __launch_bounds__(THREADS, 4)
void k_aggregate(const float* __restrict__ x,
                 const float* __restrict__ W,
                 const float* __restrict__ bias,
                 const float* __restrict__ w1, const float* __restrict__ b1,
                 const float* __restrict__ w2, const float* __restrict__ b2,
                 const float* __restrict__ w3, const float* __restrict__ b3,
                 float* __restrict__ out) {
    extern __shared__ float smem[];
    float* S   = smem + SM_S_OFF;
    float* Wsh = smem + SM_W_OFF;
    unsigned short* listAll = (unsigned short*)(smem + SM_LIST_OFF);

    const int tid  = threadIdx.x;
    const int warp = tid >> 5;
    const int lane = tid & 31;
    const int g    = blockIdx.x >> 3;            // 8 blocks/graph

    // ---- stage W (swizzled) ----
    for (int idx = tid; idx < 64 * 64; idx += THREADS) {
        int k = idx >> 6, d = idx & 63;
        Wsh[k * W_STRIDE + wphys(d & ~3) + (d & 3)] = W[idx];
    }

    // ---- Phase A: gather ----
    {
        const int h   = lane >> 4;
        const int l16 = lane & 15;
        const int off = l16 << 2;
        unsigned short* lst = listAll + warp * LISTCAP;
        const float* xg = x + ((size_t)g << 16);

        const int rowBase = blockIdx.x * ROWS_PER_BLOCK + warp * 16;
        unsigned wordNext = g_adj[rowBase * ROW_WORDS + lane];

        for (int i = 0; i < 16; i++) {
            const int lr = warp * 16 + i;
            unsigned word = wordNext;
            if (i < 15)
                wordNext = g_adj[(rowBase + i + 1) * ROW_WORDS + lane];
            g_adj[(rowBase + i) * ROW_WORDS + lane] = 0u;  // restore zeros

            // decode bitmap row -> compact neighbor list
            int cnt = __popc(word);
            int pre = cnt;
#pragma unroll
            for (int o = 1; o < 32; o <<= 1) {
                int v = __shfl_up_sync(FULLMASK, pre, o);
                if (lane >= o) pre += v;
            }
            int deg = __shfl_sync(FULLMASK, pre, 31);
            pre -= cnt;
            while (word) {
                int b = __ffs(word) - 1;
                word &= word - 1;
                if (pre < LISTCAP) lst[pre] = (unsigned short)((lane << 5) | b);
                pre++;
            }
            if (deg > LISTCAP) deg = LISTCAP;
            __syncwarp();

            // half-warp pair gather, unrolled x4, two f32x2 accumulator chains
            unsigned long long a0 = 0ull, a1 = 0ull, b0 = 0ull, b1 = 0ull;
            const int nfull = deg >> 1;
            int t = 0;
            for (; t + 4 <= nfull; t += 4) {
                int i0 = (int)lst[2 * t + h];
                int i1 = (int)lst[2 * (t + 1) + h];
                int i2 = (int)lst[2 * (t + 2) + h];
                int i3 = (int)lst[2 * (t + 3) + h];
                F4U v0, v1, v2, v3;
                v0.f = __ldg((const float4*)(xg + (i0 << 6) + off));
                v1.f = __ldg((const float4*)(xg + (i1 << 6) + off));
                v2.f = __ldg((const float4*)(xg + (i2 << 6) + off));
                v3.f = __ldg((const float4*)(xg + (i3 << 6) + off));
                a0 = add2(a0, v0.u[0]); a1 = add2(a1, v0.u[1]);
                b0 = add2(b0, v1.u[0]); b1 = add2(b1, v1.u[1]);
                a0 = add2(a0, v2.u[0]); a1 = add2(a1, v2.u[1]);
                b0 = add2(b0, v3.u[0]); b1 = add2(b1, v3.u[1]);
            }
            for (; t < nfull; t++) {
                int ni = (int)lst[2 * t + h];
                F4U v;
                v.f = __ldg((const float4*)(xg + (ni << 6) + off));
                a0 = add2(a0, v.u[0]);
                a1 = add2(a1, v.u[1]);
            }
            if ((deg & 1) && h == 0) {
                int ni = (int)lst[deg - 1];
                F4U v;
                v.f = __ldg((const float4*)(xg + (ni << 6) + off));
                b0 = add2(b0, v.u[0]);
                b1 = add2(b1, v.u[1]);
            }
            a0 = add2(a0, b0);
            a1 = add2(a1, b1);

            float s0 = lo2(a0), s1 = hi2(a0), s2 = lo2(a1), s3 = hi2(a1);
            s0 += __shfl_xor_sync(FULLMASK, s0, 16);
            s1 += __shfl_xor_sync(FULLMASK, s1, 16);
            s2 += __shfl_xor_sync(FULLMASK, s2, 16);
            s3 += __shfl_xor_sync(FULLMASK, s3, 16);
            if (h == 0) {
                // chunk-rotation swizzle: logical chunk l16 -> phys (l16 + row/4) & 15
                int pc = ((l16 + (lr >> 2)) & 15) << 2;
                *(float4*)&S[(lr << 6) + pc] = make_float4(s0, s1, s2, s3);
            }
            __syncwarp();
        }
    }
    __syncthreads();

    // ---- Phase B: Y = S@W + bias, 4 rows x 8 dims / thread, f32x2,
    //      chunked-k float4 S reads (conflict-free via rotation swizzle) ----
    const int d0    = (lane & 7) * 8;
    const int rsub  = lane >> 3;
    const int rbase = warp * 16 + rsub * 4;
    const int rq    = rbase >> 2;
    const int pc0   = wphys(d0);
    const int pc1   = wphys(d0 + 4);

    unsigned long long acc[4][4];
    {
        unsigned long long bp[4];
#pragma unroll
        for (int p = 0; p < 4; p++)
            bp[p] = pack2(__ldg(&bias[d0 + 2 * p]), __ldg(&bias[d0 + 2 * p + 1]));
#pragma unroll
        for (int i = 0; i < 4; i++)
#pragma unroll
            for (int p = 0; p < 4; p++) acc[i][p] = bp[p];
    }

#pragma unroll 4
    for (int kc = 0; kc < 16; kc++) {
        F4U sv[4];
        const int pcs = ((kc + rq) & 15) << 2;
#pragma unroll
        for (int i = 0; i < 4; i++)
            sv[i].f = *(const float4*)&S[((rbase + i) << 6) + pcs];
#pragma unroll
        for (int kk = 0; kk < 4; kk++) {
            const int k = kc * 4 + kk;
            F4U wa, wb;
            wa.f = *(const float4*)&Wsh[k * W_STRIDE + pc0];
            wb.f = *(const float4*)&Wsh[k * W_STRIDE + pc1];
#pragma unroll
            for (int i = 0; i < 4; i++) {
                float s = (kk == 0) ? sv[i].f.x : (kk == 1) ? sv[i].f.y
                        : (kk == 2) ? sv[i].f.z : sv[i].f.w;
                unsigned long long sp = pack2(s, s);
                acc[i][0] = fma2(sp, wa.u[0], acc[i][0]);
                acc[i][1] = fma2(sp, wa.u[1], acc[i][1]);
                acc[i][2] = fma2(sp, wb.u[0], acc[i][2]);
                acc[i][3] = fma2(sp, wb.u[1], acc[i][3]);
            }
        }
    }

    // ---- max-pool epilogue ----
    float m[8];
#pragma unroll
    for (int p = 0; p < 4; p++) {
        float m0 = lo2(acc[0][p]), m1 = hi2(acc[0][p]);
#pragma unroll
        for (int i = 1; i < 4; i++) {
            m0 = fmaxf(m0, lo2(acc[i][p]));
            m1 = fmaxf(m1, hi2(acc[i][p]));
        }
        m[2 * p] = m0;
        m[2 * p + 1] = m1;
    }
#pragma unroll
    for (int j = 0; j < 8; j++) {
        m[j] = fmaxf(m[j], __shfl_xor_sync(FULLMASK, m[j], 8));
        m[j] = fmaxf(m[j], __shfl_xor_sync(FULLMASK, m[j], 16));
    }
    if (rsub == 0) {
#pragma unroll
        for (int j = 0; j < 8; j++)
            atomicMax(&g_pooled[g * 64 + d0 + j], fmap(m[j]));
    }

    // ---- last block of this graph runs the MLP head inline ----
    __shared__ int s_last;
    __shared__ float mh[64];
    __shared__ float mred[4][64];
    __shared__ float moutred[2];

    __threadfence();            // order this block's atomicMax before counter
    __syncthreads();
    if (tid == 0)
        s_last = (atomicAdd(&g_cnt[g], 1) == BLOCKS_PER_GRAPH - 1);
    __syncthreads();
    if (!s_last) return;
    __threadfence();            // acquire: other blocks' pooled maxes visible

    const int d = tid & 63;
    const int q = tid >> 6;     // 0..3, k-chunk
    if (tid < 64) {
        mh[tid] = funmap(g_pooled[g * 64 + tid]);
        g_pooled[g * 64 + tid] = 0u;     // restore zeros for next call
    }
    if (tid == 0) g_cnt[g] = 0;
    __syncthreads();

    // layer 1
    {
        float p = 0.f;
        const int k0 = q * 16;
#pragma unroll
        for (int k = 0; k < 16; k++)
            p = fmaf(mh[k0 + k], __ldg(&w1[(k0 + k) * 64 + d]), p);
        mred[q][d] = p;
        __syncthreads();
        if (tid < 64)
            mh[d] = tanhf(mred[0][d] + mred[1][d] + mred[2][d] + mred[3][d]
                          + __ldg(&b1[d]));
        __syncthreads();
    }
    // layer 2
    {
        float p = 0.f;
        const int k0 = q * 16;
#pragma unroll
        for (int k = 0; k < 16; k++)
            p = fmaf(mh[k0 + k], __ldg(&w2[(k0 + k) * 64 + d]), p);
        mred[q][d] = p;
        __syncthreads();
        if (tid < 64)
            mh[d] = tanhf(mred[0][d] + mred[1][d] + mred[2][d] + mred[3][d]
                          + __ldg(&b2[d]));
        __syncthreads();
    }
    // layer 3
    if (tid < 64) {
        float p = mh[tid] * __ldg(&w3[tid]);
#pragma unroll
        for (int o = 16; o; o >>= 1) p += __shfl_xor_sync(FULLMASK, p, o);
        if ((tid & 31) == 0) moutred[tid >> 5] = p;
    }
    __syncthreads();
    if (tid == 0) out[g] = moutred[0] + moutred[1] + __ldg(&b3[0]);
}

// ---------------------------------------------------------------------------
extern "C" void kernel_launch(void* const* d_in, const int* in_sizes, int n_in,
                              void* d_out, int out_size) {
    const float* x      = (const float*)d_in[0];
    const void*  eidx   = d_in[1];
    const float* weight = (const float*)d_in[4];
    const float* bias   = (const float*)d_in[5];
    const float* w1     = (const float*)d_in[6];
    const float* b1     = (const float*)d_in[7];
    const float* w2     = (const float*)d_in[8];
    const float* b2     = (const float*)d_in[9];
    const float* w3     = (const float*)d_in[10];
    const float* b3     = (const float*)d_in[11];
    float* out = (float*)d_out;

    cudaFuncSetAttribute(k_aggregate, cudaFuncAttributeMaxDynamicSharedMemorySize, SM_BYTES);

    k_scatter<<<(EDGES / 2 + 255) / 256, 256>>>(eidx);

    k_aggregate<<<NNODES / ROWS_PER_BLOCK, THREADS, SM_BYTES>>>(
        x, weight, bias, w1, b1, w2, b2, w3, b3, out);
}